// round 13
// baseline (speedup 1.0000x reference)
#include <cuda_runtime.h>
#include <math_constants.h>
#include <stdint.h>

#define BB 2
#define SS 2048
#define DD 1024
#define HH 16
#define DHH 64
#define SCALE 0.125f  // DH^-0.5

// ---------------- scratch (no allocations allowed) ----------------
__device__ float g_xt[BB * SS * DD];                     // x, tf32-rounded
__device__ float g_w[4 * DD * DD];                       // wq,wk,wv,wo tf32-rounded
__device__ float g_bqk[2 * DD];                          // packed q,k biases
__device__ float g_qk[2 * BB * SS * DD];                 // q then k (rounded)
__device__ float g_vt[BB * DD * SS];                     // v transposed [b*D+d][s] (rounded)
__device__ float g_ctx[BB * SS * DD];                    // context (rounded)
__device__ uint32_t g_pmask[BB * SS * SS / 32];          // bit-packed mask (1MB)
__device__ float g_attn[(long long)BB * HH * SS * SS];   // fallback if attn not exported

// ---------------- tf32 helpers ----------------
__device__ __forceinline__ float f2tf(float x) {
    uint32_t u;
    asm("cvt.rna.tf32.f32 %0, %1;" : "=r"(u) : "f"(x));
    return __uint_as_float(u);
}

__device__ __forceinline__ void mma8(float* c, const uint32_t* a, const uint32_t* b) {
    asm volatile(
        "mma.sync.aligned.m16n8k8.row.col.f32.tf32.tf32.f32 "
        "{%0,%1,%2,%3}, {%4,%5,%6,%7}, {%8,%9}, {%0,%1,%2,%3};\n"
        : "+f"(c[0]), "+f"(c[1]), "+f"(c[2]), "+f"(c[3])
        : "r"(a[0]), "r"(a[1]), "r"(a[2]), "r"(a[3]),
          "r"(b[0]), "r"(b[1]));
}

__device__ __forceinline__ void cpa16(uint32_t s, const void* g) {
    asm volatile("cp.async.cg.shared.global [%0], [%1], 16;" :: "r"(s), "l"(g) : "memory");
}
__device__ __forceinline__ void cp_commit() {
    asm volatile("cp.async.commit_group;" ::: "memory");
}
template <int N>
__device__ __forceinline__ void cp_wait() {
    asm volatile("cp.async.wait_group %0;" :: "n"(N) : "memory");
}

// ---------------- small prep kernels ----------------
__global__ void conv_tf32(const float4* __restrict__ src, float4* __restrict__ dst, int n4) {
    int i = blockIdx.x * 256 + threadIdx.x;
    if (i < n4) {
        float4 v = src[i];
        v.x = f2tf(v.x); v.y = f2tf(v.y); v.z = f2tf(v.z); v.w = f2tf(v.w);
        dst[i] = v;
    }
}
__global__ void pack_bias2(const float* __restrict__ a, const float* __restrict__ b,
                           float* __restrict__ dst) {
    int i = blockIdx.x * 256 + threadIdx.x;
    if (i < DD) { dst[i] = a[i]; dst[DD + i] = b[i]; }
}
__global__ void pack_mask(const int* __restrict__ m, uint32_t* __restrict__ pm, int nwords) {
    int gtid = blockIdx.x * 256 + threadIdx.x;
    int wid = gtid >> 5, lane = gtid & 31;
    if (wid < nwords) {
        int v = m[(long long)wid * 32 + lane];
        uint32_t bits = __ballot_sync(0xFFFFFFFF, v != 0);
        if (lane == 0) pm[wid] = bits;
    }
}

// =================================================================
// TF32 GEMM, cp.async double-buffered (used for projections + out).
//   A: [m][k] k-contig, B: [n][k] k-contig. C = alpha*A.B^T (+bias)
//   smem rows chunk-XOR swizzled.  ROUND_C: tf32-round outputs.
//   TRANS_C: scatter C transposed into g_vt layout.
// =================================================================
template <int BM, int BN, int BK, int WM, int WN, bool ROUND_C, bool TRANS_C>
__global__ __launch_bounds__(256, 2) void gemm_cp(
    const float* __restrict__ A, const float* __restrict__ Bm,
    const float* __restrict__ bias, float* __restrict__ C,
    int K, int lda, int ldbn, int ldc,
    long long aS1, long long bS1, long long cS1,
    long long biasS1, float alpha)
{
    constexpr int WARPS_M = BM / WM;
    constexpr int MT = WM / 16;
    constexpr int NT = WN / 8;
    constexpr int AF = BM * 8 / 256;
    constexpr int BF = BN * 8 / 256;

    int z = blockIdx.z;
    A  += z * aS1;
    Bm += z * bS1;
    C  += z * cS1;
    const float* biasp = bias ? bias + z * biasS1 : nullptr;

    __shared__ float As[2][BM * BK];
    __shared__ float Bs[2][BN * BK];

    int tid  = threadIdx.x;
    int lane = tid & 31, warp = tid >> 5;
    int gid = lane >> 2, tig = lane & 3;
    int warp_m = (warp % WARPS_M) * WM;
    int warp_n = (warp / WARPS_M) * WN;
    int m0 = blockIdx.y * BM, n0 = blockIdx.x * BN;

    int rbase = tid >> 3;
    int cch   = tid & 7;
    int scol  = ((cch ^ (rbase & 7)) << 2);
    uint32_t sA0 = (uint32_t)__cvta_generic_to_shared(&As[0][0]);
    uint32_t sB0 = (uint32_t)__cvta_generic_to_shared(&Bs[0][0]);
    uint32_t sAoff = (uint32_t)((rbase * BK + scol) * 4);

    int kt_total = K / BK;

    auto load_stage = [&](int st, int k0) {
        uint32_t sa = sA0 + st * (BM * BK * 4) + sAoff;
        const float* ga = A + (long long)(m0 + rbase) * lda + k0 + cch * 4;
        #pragma unroll
        for (int i = 0; i < AF; i++)
            cpa16(sa + i * 32 * BK * 4, ga + (long long)i * 32 * lda);
        uint32_t sb = sB0 + st * (BN * BK * 4) + sAoff;
        const float* gb = Bm + (long long)(n0 + rbase) * ldbn + k0 + cch * 4;
        #pragma unroll
        for (int i = 0; i < BF; i++)
            cpa16(sb + i * 32 * BK * 4, gb + (long long)i * 32 * ldbn);
    };

    float acc[MT][NT][4] = {};
    int mb[MT], nb[NT];
    #pragma unroll
    for (int i = 0; i < MT; i++) mb[i] = warp_m + i * 16 + gid;
    #pragma unroll
    for (int j = 0; j < NT; j++) nb[j] = warp_n + j * 8 + gid;

    load_stage(0, 0);
    cp_commit();

    for (int kt = 0; kt < kt_total; kt++) {
        int cur = kt & 1;
        if (kt + 1 < kt_total) {
            load_stage(cur ^ 1, (kt + 1) * BK);
            cp_commit();
            cp_wait<1>();
        } else {
            cp_wait<0>();
        }
        __syncthreads();

        const float* Ac = As[cur];
        const float* Bc = Bs[cur];
        #pragma unroll
        for (int ks = 0; ks < BK; ks += 8) {
            int c0 = ks >> 2;
            int s0 = ((c0 ^ gid) << 2) + tig;
            int s1 = (((c0 + 1) ^ gid) << 2) + tig;
            uint32_t af[MT][4], bf[NT][2];
            #pragma unroll
            for (int i = 0; i < MT; i++) {
                af[i][0] = __float_as_uint(Ac[mb[i] * BK + s0]);
                af[i][1] = __float_as_uint(Ac[(mb[i] + 8) * BK + s0]);
                af[i][2] = __float_as_uint(Ac[mb[i] * BK + s1]);
                af[i][3] = __float_as_uint(Ac[(mb[i] + 8) * BK + s1]);
            }
            #pragma unroll
            for (int j = 0; j < NT; j++) {
                bf[j][0] = __float_as_uint(Bc[nb[j] * BK + s0]);
                bf[j][1] = __float_as_uint(Bc[nb[j] * BK + s1]);
            }
            #pragma unroll
            for (int i = 0; i < MT; i++)
                #pragma unroll
                for (int j = 0; j < NT; j++)
                    mma8(acc[i][j], af[i], bf[j]);
        }
        __syncthreads();
    }

    #pragma unroll
    for (int i = 0; i < MT; i++) {
        int r0 = m0 + warp_m + i * 16 + gid;
        #pragma unroll
        for (int j = 0; j < NT; j++) {
            int c0 = n0 + warp_n + j * 8 + tig * 2;
            float2 bv = make_float2(0.f, 0.f);
            if (biasp) bv = *(const float2*)&biasp[c0];
            float v00 = acc[i][j][0] * alpha + bv.x;
            float v01 = acc[i][j][1] * alpha + bv.y;
            float v10 = acc[i][j][2] * alpha + bv.x;
            float v11 = acc[i][j][3] * alpha + bv.y;
            if (ROUND_C) {
                v00 = f2tf(v00); v01 = f2tf(v01); v10 = f2tf(v10); v11 = f2tf(v11);
            }
            if (TRANS_C) {
                int b0 = r0 >> 11, s0r = r0 & (SS - 1);
                int b1 = (r0 + 8) >> 11, s1r = (r0 + 8) & (SS - 1);
                C[((long long)(b0 * DD + c0)) * SS + s0r]     = v00;
                C[((long long)(b0 * DD + c0 + 1)) * SS + s0r] = v01;
                C[((long long)(b1 * DD + c0)) * SS + s1r]     = v10;
                C[((long long)(b1 * DD + c0 + 1)) * SS + s1r] = v11;
            } else {
                *(float2*)&C[(long long)r0 * ldc + c0]       = make_float2(v00, v01);
                *(float2*)&C[(long long)(r0 + 8) * ldc + c0] = make_float2(v10, v11);
            }
        }
    }
}

// =================================================================
// Fused attention: per block = 16 q-rows of one (b,h).
//   Phase 1: scores = SCALE * Q Kh^T into smem (16 x 2048)
//   Phase 2: masked softmax in smem (bit-packed mask, L2-hot);
//            writes normalized attn to gmem; keeps tf32 p in smem
//   Phase 3: ctx = (P @ V) * inv  (V streamed via cp.async)
// =================================================================
#define QB 16
#define SCR_LD 2052   // 2052 & 31 == 4 -> conflict-free fragment/sweep access
#define QLD 68
#define KLD 68
#define FUSED_SMEM ((QB * SCR_LD + QB * QLD + 2 * 128 * KLD) * 4)

__global__ __launch_bounds__(256, 1) void fused_attn(
    const float* __restrict__ qk, const float* __restrict__ vt,
    const uint32_t* __restrict__ pmask,
    float* __restrict__ attn, float* __restrict__ ctx)
{
    extern __shared__ float sm[];
    float* sc = sm;                       // [16][SCR_LD]
    float* sq = sc + QB * SCR_LD;         // [16][QLD]
    float* kb = sq + QB * QLD;            // [2][128*KLD]
    __shared__ float sinv[QB];

    int q0 = blockIdx.x * QB;
    int bh = blockIdx.y;                  // b*H + h
    int b = bh >> 4, h = bh & 15;

    int tid = threadIdx.x;
    int lane = tid & 31, warp = tid >> 5;
    int gid = lane >> 2, tig = lane & 3;

    const float* Q  = qk + (long long)(b * SS + q0) * DD + h * DHH;
    const float* Kh = qk + (long long)(BB * SS) * DD + (long long)b * SS * DD + h * DHH;
    const float* Vh = vt + (long long)(b * DD + h * DHH) * SS;

    // load Q tile 16x64 -> sq (float4; QLD*4 and 16-float chunks are 16B aligned)
    {
        int row = tid >> 4, qc = tid & 15;
        float4 v = *(const float4*)&Q[(long long)row * DD + qc * 4];
        *(float4*)&sq[row * QLD + qc * 4] = v;
    }

    int krow = tid >> 4, kch = tid & 15;

    auto loadK = [&](int buf, int nc) {
        uint32_t base = (uint32_t)__cvta_generic_to_shared(kb + buf * (128 * KLD));
        const float* g = Kh + (long long)(nc * 128 + krow) * DD + kch * 4;
        uint32_t s = base + (uint32_t)(krow * KLD + kch * 4) * 4;
        #pragma unroll
        for (int i = 0; i < 8; i++)
            cpa16(s + i * 16 * KLD * 4, g + (long long)i * 16 * DD);
    };
    auto loadV = [&](int buf, int kc) {
        uint32_t base = (uint32_t)__cvta_generic_to_shared(kb + buf * (128 * KLD));
        const float* g = Vh + (long long)krow * SS + kc * 64 + kch * 4;
        uint32_t s = base + (uint32_t)(krow * KLD + kch * 4) * 4;
        #pragma unroll
        for (int i = 0; i < 4; i++)
            cpa16(s + i * 16 * KLD * 4, g + (long long)i * 16 * SS);
    };

    // ================= Phase 1: scores =================
    loadK(0, 0); cp_commit();
    for (int nc = 0; nc < 16; nc++) {
        int cur = nc & 1;
        if (nc + 1 < 16) { loadK(cur ^ 1, nc + 1); cp_commit(); cp_wait<1>(); }
        else cp_wait<0>();
        __syncthreads();
        const float* Kc = kb + cur * (128 * KLD);
        float acc[2][4] = {};
        int nb0 = warp * 16;
        #pragma unroll
        for (int ks = 0; ks < 64; ks += 8) {
            uint32_t af[4], bf0[2], bf1[2];
            af[0] = __float_as_uint(sq[gid * QLD + ks + tig]);
            af[1] = __float_as_uint(sq[(gid + 8) * QLD + ks + tig]);
            af[2] = __float_as_uint(sq[gid * QLD + ks + tig + 4]);
            af[3] = __float_as_uint(sq[(gid + 8) * QLD + ks + tig + 4]);
            bf0[0] = __float_as_uint(Kc[(nb0 + gid) * KLD + ks + tig]);
            bf0[1] = __float_as_uint(Kc[(nb0 + gid) * KLD + ks + tig + 4]);
            bf1[0] = __float_as_uint(Kc[(nb0 + 8 + gid) * KLD + ks + tig]);
            bf1[1] = __float_as_uint(Kc[(nb0 + 8 + gid) * KLD + ks + tig + 4]);
            mma8(acc[0], af, bf0);
            mma8(acc[1], af, bf1);
        }
        #pragma unroll
        for (int j = 0; j < 2; j++) {
            int col = nc * 128 + nb0 + j * 8 + tig * 2;
            sc[gid * SCR_LD + col]           = acc[j][0] * SCALE;
            sc[gid * SCR_LD + col + 1]       = acc[j][1] * SCALE;
            sc[(gid + 8) * SCR_LD + col]     = acc[j][2] * SCALE;
            sc[(gid + 8) * SCR_LD + col + 1] = acc[j][3] * SCALE;
        }
        __syncthreads();
    }

    // ================= Phase 2: softmax =================
    #pragma unroll
    for (int rr = 0; rr < 2; rr++) {
        int row = warp * 2 + rr;
        int sgl = q0 + row;
        const uint32_t* mrow = pmask + ((long long)b * SS + sgl) * 64;
        uint32_t w0 = mrow[lane], w1 = mrow[lane + 32];
        float* srow = sc + row * SCR_LD;

        float mx = -CUDART_INF_F;
        for (int i = 0; i < 32; i++) {
            uint32_t wrd = __shfl_sync(0xFFFFFFFF, w0, i);
            float v = srow[i * 32 + lane];
            v = ((wrd >> lane) & 1u) ? v : -1e9f;
            srow[i * 32 + lane] = v;
            mx = fmaxf(mx, v);
        }
        for (int i = 0; i < 32; i++) {
            uint32_t wrd = __shfl_sync(0xFFFFFFFF, w1, i);
            float v = srow[(32 + i) * 32 + lane];
            v = ((wrd >> lane) & 1u) ? v : -1e9f;
            srow[(32 + i) * 32 + lane] = v;
            mx = fmaxf(mx, v);
        }
        #pragma unroll
        for (int o = 16; o > 0; o >>= 1)
            mx = fmaxf(mx, __shfl_xor_sync(0xFFFFFFFF, mx, o));

        float sum = 0.f;
        for (int i = 0; i < 64; i++) {
            float v = srow[i * 32 + lane];
            float p = __expf(v - mx);
            sum += p;
            srow[i * 32 + lane] = f2tf(p);
        }
        #pragma unroll
        for (int o = 16; o > 0; o >>= 1)
            sum += __shfl_xor_sync(0xFFFFFFFF, sum, o);
        float inv = 1.f / sum;
        if (lane == 0) sinv[row] = inv;

        float* arow = attn + ((long long)bh * SS + sgl) * SS;
        for (int i = 0; i < 64; i++) {
            float p = srow[i * 32 + lane];
            arow[i * 32 + lane] = p * inv;
        }
    }
    __syncthreads();

    // ================= Phase 3: ctx = (P @ V) * inv =================
    float acc[4] = {};
    int n0 = warp * 8;
    loadV(0, 0); cp_commit();
    for (int kc = 0; kc < 32; kc++) {
        int cur = kc & 1;
        if (kc + 1 < 32) { loadV(cur ^ 1, kc + 1); cp_commit(); cp_wait<1>(); }
        else cp_wait<0>();
        __syncthreads();
        const float* Vc = kb + cur * (128 * KLD);
        #pragma unroll
        for (int ks = 0; ks < 64; ks += 8) {
            int kg = kc * 64 + ks;
            uint32_t af[4], bf[2];
            af[0] = __float_as_uint(sc[gid * SCR_LD + kg + tig]);
            af[1] = __float_as_uint(sc[(gid + 8) * SCR_LD + kg + tig]);
            af[2] = __float_as_uint(sc[gid * SCR_LD + kg + tig + 4]);
            af[3] = __float_as_uint(sc[(gid + 8) * SCR_LD + kg + tig + 4]);
            bf[0] = __float_as_uint(Vc[(n0 + gid) * KLD + ks + tig]);
            bf[1] = __float_as_uint(Vc[(n0 + gid) * KLD + ks + tig + 4]);
            mma8(acc, af, bf);
        }
        __syncthreads();
    }
    {
        float i0 = sinv[gid], i1 = sinv[gid + 8];
        int c = n0 + tig * 2;
        float2 v0 = make_float2(f2tf(acc[0] * i0), f2tf(acc[1] * i0));
        float2 v1 = make_float2(f2tf(acc[2] * i1), f2tf(acc[3] * i1));
        *(float2*)&ctx[(long long)(b * SS + q0 + gid) * DD + h * DHH + c]     = v0;
        *(float2*)&ctx[(long long)(b * SS + q0 + gid + 8) * DD + h * DHH + c] = v1;
    }
}

// ---------------- launch ----------------
extern "C" void kernel_launch(void* const* d_in, const int* in_sizes, int n_in,
                              void* d_out, int out_size)
{
    const float* x    = (const float*)d_in[0];
    const int*   mask = (const int*)  d_in[1];
    const float* wq_w = (const float*)d_in[2];
    const float* wq_b = (const float*)d_in[3];
    const float* wk_w = (const float*)d_in[4];
    const float* wk_b = (const float*)d_in[5];
    const float* wv_w = (const float*)d_in[6];
    const float* wv_b = (const float*)d_in[7];
    const float* wo_w = (const float*)d_in[8];
    const float* wo_b = (const float*)d_in[9];

    float* out = (float*)d_out;

    const long long OUT_ELEMS  = (long long)BB * SS * DD;
    const long long ATTN_ELEMS = (long long)BB * HH * SS * SS;

    float *xt, *w, *bqk, *qk, *vt, *ctx, *attn;
    uint32_t* pm;
    cudaGetSymbolAddress((void**)&xt,  g_xt);
    cudaGetSymbolAddress((void**)&w,   g_w);
    cudaGetSymbolAddress((void**)&bqk, g_bqk);
    cudaGetSymbolAddress((void**)&qk,  g_qk);
    cudaGetSymbolAddress((void**)&vt,  g_vt);
    cudaGetSymbolAddress((void**)&ctx, g_ctx);
    cudaGetSymbolAddress((void**)&pm,  g_pmask);
    if ((long long)out_size >= OUT_ELEMS + ATTN_ELEMS) {
        attn = out + OUT_ELEMS;
    } else {
        cudaGetSymbolAddress((void**)&attn, g_attn);
    }

    const int M = BB * SS;           // 4096
    const int WELE = DD * DD;

    // 0) prep: tf32-round x/weights, pack biases, bit-pack mask
    conv_tf32<<<(M * DD / 4 + 255) / 256, 256>>>((const float4*)x, (float4*)xt, M * DD / 4);
    conv_tf32<<<(WELE / 4 + 255) / 256, 256>>>((const float4*)wq_w, (float4*)(w + 0 * WELE), WELE / 4);
    conv_tf32<<<(WELE / 4 + 255) / 256, 256>>>((const float4*)wk_w, (float4*)(w + 1 * WELE), WELE / 4);
    conv_tf32<<<(WELE / 4 + 255) / 256, 256>>>((const float4*)wv_w, (float4*)(w + 2 * WELE), WELE / 4);
    conv_tf32<<<(WELE / 4 + 255) / 256, 256>>>((const float4*)wo_w, (float4*)(w + 3 * WELE), WELE / 4);
    pack_bias2<<<(DD + 255) / 256, 256>>>(wq_b, wk_b, bqk);
    {
        int nwords = BB * SS * SS / 32;
        pack_mask<<<(nwords * 32 + 255) / 256, 256>>>(mask, pm, nwords);
    }

    // 1) Q and K projections in one launch (z=0:Q, z=1:K), rounded outputs
    {
        dim3 grid(DD / 128, M / 128, 2);
        gemm_cp<128, 128, 32, 64, 32, true, false><<<grid, 256>>>(
            xt, w, bqk, qk, DD, DD, DD, DD,
            0, (long long)WELE, (long long)M * DD, DD, 1.0f);
    }
    // 1b) V projection, transposed + rounded into g_vt
    {
        dim3 grid(DD / 128, M / 128, 1);
        gemm_cp<128, 128, 32, 64, 32, true, true><<<grid, 256>>>(
            xt, w + 2 * WELE, wv_b, vt, DD, DD, DD, 0,
            0, 0, 0, 0, 1.0f);
    }

    // 2) fused scores + softmax + AV
    {
        cudaFuncSetAttribute(fused_attn,
            cudaFuncAttributeMaxDynamicSharedMemorySize, FUSED_SMEM);
        dim3 grid(SS / QB, BB * HH);
        fused_attn<<<grid, 256, FUSED_SMEM>>>(qk, vt, pm, attn, ctx);
    }

    // 3) out = ctx @ wo^T + wo_b
    {
        dim3 grid(DD / 128, M / 128, 1);
        gemm_cp<128, 128, 32, 64, 32, false, false><<<grid, 256>>>(
            ctx, w + 3 * WELE, wo_b, out, DD, DD, DD, DD,
            0, 0, 0, 0, 1.0f);
    }
}

// round 14
// speedup vs baseline: 1.6847x; 1.6847x over previous
#include <cuda_runtime.h>
#include <math_constants.h>
#include <stdint.h>

#define BB 2
#define SS 2048
#define DD 1024
#define HH 16
#define DHH 64
#define SCALE 0.125f  // DH^-0.5

// ---------------- scratch (no allocations allowed) ----------------
__device__ float g_xt[BB * SS * DD];                     // x, tf32-rounded
__device__ float g_w[4 * DD * DD];                       // wq,wk,wv,wo tf32-rounded
__device__ float g_bqk[2 * DD];                          // packed q,k biases
__device__ float g_qk[2 * BB * SS * DD];                 // q then k (rounded)
__device__ float g_vt[BB * DD * SS];                     // v transposed [b*D+d][s] (rounded)
__device__ float g_ctx[BB * SS * DD];                    // context (rounded)
__device__ uint32_t g_pmask[BB * SS * SS / 32];          // bit-packed mask (1MB, L2-hot)
__device__ float g_attn[(long long)BB * HH * SS * SS];   // fallback if attn not exported

// ---------------- tf32 helpers ----------------
__device__ __forceinline__ float f2tf(float x) {
    uint32_t u;
    asm("cvt.rna.tf32.f32 %0, %1;" : "=r"(u) : "f"(x));
    return __uint_as_float(u);
}

__device__ __forceinline__ void mma8(float* c, const uint32_t* a, const uint32_t* b) {
    asm volatile(
        "mma.sync.aligned.m16n8k8.row.col.f32.tf32.tf32.f32 "
        "{%0,%1,%2,%3}, {%4,%5,%6,%7}, {%8,%9}, {%0,%1,%2,%3};\n"
        : "+f"(c[0]), "+f"(c[1]), "+f"(c[2]), "+f"(c[3])
        : "r"(a[0]), "r"(a[1]), "r"(a[2]), "r"(a[3]),
          "r"(b[0]), "r"(b[1]));
}

__device__ __forceinline__ void cpa16(uint32_t s, const void* g) {
    asm volatile("cp.async.cg.shared.global [%0], [%1], 16;" :: "r"(s), "l"(g) : "memory");
}
__device__ __forceinline__ void cp_commit() {
    asm volatile("cp.async.commit_group;" ::: "memory");
}
template <int N>
__device__ __forceinline__ void cp_wait() {
    asm volatile("cp.async.wait_group %0;" :: "n"(N) : "memory");
}

// ---------------- prep kernels ----------------
__global__ void conv_tf32(const float4* __restrict__ src, float4* __restrict__ dst, int n4) {
    int i = blockIdx.x * 256 + threadIdx.x;
    if (i < n4) {
        float4 v = src[i];
        v.x = f2tf(v.x); v.y = f2tf(v.y); v.z = f2tf(v.z); v.w = f2tf(v.w);
        dst[i] = v;
    }
}
// 4 weight matrices in one z-batched launch
__global__ void conv_tf32_w(const float4* __restrict__ w0, const float4* __restrict__ w1,
                            const float4* __restrict__ w2, const float4* __restrict__ w3,
                            float4* __restrict__ dst, int n4) {
    int i = blockIdx.x * 256 + threadIdx.x;
    if (i >= n4) return;
    const float4* src = (blockIdx.z == 0) ? w0 : (blockIdx.z == 1) ? w1
                       : (blockIdx.z == 2) ? w2 : w3;
    float4 v = src[i];
    v.x = f2tf(v.x); v.y = f2tf(v.y); v.z = f2tf(v.z); v.w = f2tf(v.w);
    dst[(long long)blockIdx.z * n4 + i] = v;
}
__global__ void pack_bias2(const float* __restrict__ a, const float* __restrict__ b,
                           float* __restrict__ dst) {
    int i = blockIdx.x * 256 + threadIdx.x;
    if (i < DD) { dst[i] = a[i]; dst[DD + i] = b[i]; }
}
__global__ void pack_mask(const int* __restrict__ m, uint32_t* __restrict__ pm, int nwords) {
    int gtid = blockIdx.x * 256 + threadIdx.x;
    int wid = gtid >> 5, lane = gtid & 31;
    if (wid < nwords) {
        int v = m[(long long)wid * 32 + lane];
        uint32_t bits = __ballot_sync(0xFFFFFFFF, v != 0);
        if (lane == 0) pm[wid] = bits;
    }
}

// =================================================================
// TF32 GEMM, cp.async double-buffered.
//   A: [m][k] k-contig, B: [n][k] k-contig. C = alpha*A.B^T (+bias)
//   smem rows chunk-XOR swizzled (conflict-free fills + fragment LDS).
//   CONVA: tf32-round A fragments at load (fp32 attn operand)
//   ROUND_C: tf32-round outputs at store (producer-side rounding)
//   TRANS_C: scatter-store C transposed into g_vt layout
// =================================================================
template <int BM, int BN, int BK, int WM, int WN, bool CONVA, bool ROUND_C, bool TRANS_C>
__global__ __launch_bounds__(256, 2) void gemm_cp(
    const float* __restrict__ A, const float* __restrict__ Bm,
    const float* __restrict__ bias, float* __restrict__ C,
    int K, int lda, int ldbn, int ldc,
    long long aS1, long long aS2,
    long long bS1, long long bS2,
    long long cS1, long long cS2,
    long long biasS1, int Z2,
    float alpha)
{
    constexpr int WARPS_M = BM / WM;
    constexpr int MT = WM / 16;
    constexpr int NT = WN / 8;
    constexpr int AF = BM * 8 / 256;
    constexpr int BF = BN * 8 / 256;

    int z = blockIdx.z;
    int z1 = z / Z2, z2 = z % Z2;
    A  += z1 * aS1 + z2 * aS2;
    Bm += z1 * bS1 + z2 * bS2;
    C  += z1 * cS1 + z2 * cS2;
    const float* biasp = bias ? bias + z1 * biasS1 : nullptr;

    __shared__ float As[2][BM * BK];
    __shared__ float Bs[2][BN * BK];

    int tid  = threadIdx.x;
    int lane = tid & 31, warp = tid >> 5;
    int gid = lane >> 2, tig = lane & 3;
    int warp_m = (warp % WARPS_M) * WM;
    int warp_n = (warp / WARPS_M) * WN;
    int m0 = blockIdx.y * BM, n0 = blockIdx.x * BN;

    int rbase = tid >> 3;
    int cch   = tid & 7;
    int scol  = ((cch ^ (rbase & 7)) << 2);
    uint32_t sA0 = (uint32_t)__cvta_generic_to_shared(&As[0][0]);
    uint32_t sB0 = (uint32_t)__cvta_generic_to_shared(&Bs[0][0]);
    uint32_t sAoff = (uint32_t)((rbase * BK + scol) * 4);

    int kt_total = K / BK;

    auto load_stage = [&](int st, int k0) {
        uint32_t sa = sA0 + st * (BM * BK * 4) + sAoff;
        const float* ga = A + (long long)(m0 + rbase) * lda + k0 + cch * 4;
        #pragma unroll
        for (int i = 0; i < AF; i++)
            cpa16(sa + i * 32 * BK * 4, ga + (long long)i * 32 * lda);
        uint32_t sb = sB0 + st * (BN * BK * 4) + sAoff;
        const float* gb = Bm + (long long)(n0 + rbase) * ldbn + k0 + cch * 4;
        #pragma unroll
        for (int i = 0; i < BF; i++)
            cpa16(sb + i * 32 * BK * 4, gb + (long long)i * 32 * ldbn);
    };

    float acc[MT][NT][4] = {};
    int mb[MT], nb[NT];
    #pragma unroll
    for (int i = 0; i < MT; i++) mb[i] = warp_m + i * 16 + gid;
    #pragma unroll
    for (int j = 0; j < NT; j++) nb[j] = warp_n + j * 8 + gid;

    load_stage(0, 0);
    cp_commit();

    for (int kt = 0; kt < kt_total; kt++) {
        int cur = kt & 1;
        if (kt + 1 < kt_total) {
            load_stage(cur ^ 1, (kt + 1) * BK);
            cp_commit();
            cp_wait<1>();
        } else {
            cp_wait<0>();
        }
        __syncthreads();

        const float* Ac = As[cur];
        const float* Bc = Bs[cur];
        #pragma unroll
        for (int ks = 0; ks < BK; ks += 8) {
            int c0 = ks >> 2;
            int s0 = ((c0 ^ gid) << 2) + tig;
            int s1 = (((c0 + 1) ^ gid) << 2) + tig;
            uint32_t af[MT][4], bf[NT][2];
            #pragma unroll
            for (int i = 0; i < MT; i++) {
                float a0 = Ac[mb[i] * BK + s0];
                float a1 = Ac[(mb[i] + 8) * BK + s0];
                float a2 = Ac[mb[i] * BK + s1];
                float a3 = Ac[(mb[i] + 8) * BK + s1];
                if (CONVA) { a0 = f2tf(a0); a1 = f2tf(a1); a2 = f2tf(a2); a3 = f2tf(a3); }
                af[i][0] = __float_as_uint(a0);
                af[i][1] = __float_as_uint(a1);
                af[i][2] = __float_as_uint(a2);
                af[i][3] = __float_as_uint(a3);
            }
            #pragma unroll
            for (int j = 0; j < NT; j++) {
                bf[j][0] = __float_as_uint(Bc[nb[j] * BK + s0]);
                bf[j][1] = __float_as_uint(Bc[nb[j] * BK + s1]);
            }
            #pragma unroll
            for (int i = 0; i < MT; i++)
                #pragma unroll
                for (int j = 0; j < NT; j++)
                    mma8(acc[i][j], af[i], bf[j]);
        }
        __syncthreads();
    }

    #pragma unroll
    for (int i = 0; i < MT; i++) {
        int r0 = m0 + warp_m + i * 16 + gid;
        #pragma unroll
        for (int j = 0; j < NT; j++) {
            int c0 = n0 + warp_n + j * 8 + tig * 2;
            float2 bv = make_float2(0.f, 0.f);
            if (biasp) bv = *(const float2*)&biasp[c0];
            float v00 = acc[i][j][0] * alpha + bv.x;
            float v01 = acc[i][j][1] * alpha + bv.y;
            float v10 = acc[i][j][2] * alpha + bv.x;
            float v11 = acc[i][j][3] * alpha + bv.y;
            if (ROUND_C) {
                v00 = f2tf(v00); v01 = f2tf(v01); v10 = f2tf(v10); v11 = f2tf(v11);
            }
            if (TRANS_C) {
                int b0 = r0 >> 11, s0r = r0 & (SS - 1);
                int b1 = (r0 + 8) >> 11, s1r = (r0 + 8) & (SS - 1);
                C[((long long)(b0 * DD + c0)) * SS + s0r]     = v00;
                C[((long long)(b0 * DD + c0 + 1)) * SS + s0r] = v01;
                C[((long long)(b1 * DD + c0)) * SS + s1r]     = v10;
                C[((long long)(b1 * DD + c0 + 1)) * SS + s1r] = v11;
            } else {
                *(float2*)&C[(long long)r0 * ldc + c0]       = make_float2(v00, v01);
                *(float2*)&C[(long long)(r0 + 8) * ldc + c0] = make_float2(v10, v11);
            }
        }
    }
}

// ---------------- row softmax (in place), float4, bit-packed mask ----------------
__global__ __launch_bounds__(256) void softmax_rows(
    float* __restrict__ attn, const uint32_t* __restrict__ pmask)
{
    long long r = blockIdx.x;  // 0 .. B*H*S-1
    int q = (int)(r % SS);
    int b = (int)(r / ((long long)HH * SS));
    float* row = attn + r * (long long)SS;
    const uint32_t* mrow = pmask + ((long long)b * SS + q) * (SS / 32);

    int tid = threadIdx.x;
    // thread handles columns tid*4..+3 and 1024+tid*4..+3
    // mask bits: word (c>>5), nibble at bit (c&31); c = tid*4 -> word tid>>3, shift (tid&7)*4
    uint32_t mw0 = mrow[tid >> 3];
    uint32_t mw1 = mrow[32 + (tid >> 3)];
    uint32_t nib0 = (mw0 >> ((tid & 7) * 4)) & 0xF;
    uint32_t nib1 = (mw1 >> ((tid & 7) * 4)) & 0xF;

    float4 vals[2];
    float mx = -CUDART_INF_F;
    #pragma unroll
    for (int i = 0; i < 2; i++) {
        int c = (tid + i * 256) * 4;
        float4 v = *(const float4*)&row[c];
        uint32_t nib = i ? nib1 : nib0;
        if (!(nib & 1u)) v.x = -1e9f;
        if (!(nib & 2u)) v.y = -1e9f;
        if (!(nib & 4u)) v.z = -1e9f;
        if (!(nib & 8u)) v.w = -1e9f;
        vals[i] = v;
        mx = fmaxf(mx, fmaxf(fmaxf(v.x, v.y), fmaxf(v.z, v.w)));
    }

    __shared__ float red[32];
    #pragma unroll
    for (int o = 16; o > 0; o >>= 1)
        mx = fmaxf(mx, __shfl_xor_sync(0xFFFFFFFF, mx, o));
    if ((tid & 31) == 0) red[tid >> 5] = mx;
    __syncthreads();
    if (tid < 32) {
        float v = (tid < 8) ? red[tid] : -CUDART_INF_F;
        #pragma unroll
        for (int o = 4; o > 0; o >>= 1)
            v = fmaxf(v, __shfl_xor_sync(0xFFFFFFFF, v, o));
        if (tid == 0) red[0] = v;
    }
    __syncthreads();
    mx = red[0];
    __syncthreads();

    float sum = 0.f;
    #pragma unroll
    for (int i = 0; i < 2; i++) {
        vals[i].x = __expf(vals[i].x - mx);
        vals[i].y = __expf(vals[i].y - mx);
        vals[i].z = __expf(vals[i].z - mx);
        vals[i].w = __expf(vals[i].w - mx);
        sum += vals[i].x + vals[i].y + vals[i].z + vals[i].w;
    }
    #pragma unroll
    for (int o = 16; o > 0; o >>= 1)
        sum += __shfl_xor_sync(0xFFFFFFFF, sum, o);
    if ((tid & 31) == 0) red[tid >> 5] = sum;
    __syncthreads();
    if (tid < 32) {
        float v = (tid < 8) ? red[tid] : 0.f;
        #pragma unroll
        for (int o = 4; o > 0; o >>= 1)
            v += __shfl_xor_sync(0xFFFFFFFF, v, o);
        if (tid == 0) red[0] = v;
    }
    __syncthreads();
    float inv = 1.f / red[0];

    #pragma unroll
    for (int i = 0; i < 2; i++) {
        int c = (tid + i * 256) * 4;
        float4 v = vals[i];
        v.x *= inv; v.y *= inv; v.z *= inv; v.w *= inv;
        *(float4*)&row[c] = v;
    }
}

// ---------------- launch ----------------
extern "C" void kernel_launch(void* const* d_in, const int* in_sizes, int n_in,
                              void* d_out, int out_size)
{
    const float* x    = (const float*)d_in[0];
    const int*   mask = (const int*)  d_in[1];
    const float* wq_w = (const float*)d_in[2];
    const float* wq_b = (const float*)d_in[3];
    const float* wk_w = (const float*)d_in[4];
    const float* wk_b = (const float*)d_in[5];
    const float* wv_w = (const float*)d_in[6];
    const float* wv_b = (const float*)d_in[7];
    const float* wo_w = (const float*)d_in[8];
    const float* wo_b = (const float*)d_in[9];

    float* out = (float*)d_out;

    const long long OUT_ELEMS  = (long long)BB * SS * DD;
    const long long ATTN_ELEMS = (long long)BB * HH * SS * SS;

    float *xt, *w, *bqk, *qk, *vt, *ctx, *attn;
    uint32_t* pm;
    cudaGetSymbolAddress((void**)&xt,  g_xt);
    cudaGetSymbolAddress((void**)&w,   g_w);
    cudaGetSymbolAddress((void**)&bqk, g_bqk);
    cudaGetSymbolAddress((void**)&qk,  g_qk);
    cudaGetSymbolAddress((void**)&vt,  g_vt);
    cudaGetSymbolAddress((void**)&ctx, g_ctx);
    cudaGetSymbolAddress((void**)&pm,  g_pmask);
    if ((long long)out_size >= OUT_ELEMS + ATTN_ELEMS) {
        attn = out + OUT_ELEMS;
    } else {
        cudaGetSymbolAddress((void**)&attn, g_attn);
    }

    const int M = BB * SS;           // 4096
    const int WELE = DD * DD;

    // 0) prep: tf32-round x + weights (z-batched), pack biases, bit-pack mask
    conv_tf32<<<(M * DD / 4 + 255) / 256, 256>>>((const float4*)x, (float4*)xt, M * DD / 4);
    {
        dim3 grid((WELE / 4 + 255) / 256, 1, 4);
        conv_tf32_w<<<grid, 256>>>((const float4*)wq_w, (const float4*)wk_w,
                                   (const float4*)wv_w, (const float4*)wo_w,
                                   (float4*)w, WELE / 4);
    }
    pack_bias2<<<(DD + 255) / 256, 256>>>(wq_b, wk_b, bqk);
    {
        int nwords = BB * SS * SS / 32;
        pack_mask<<<(nwords * 32 + 255) / 256, 256>>>(mask, pm, nwords);
    }

    // 1) Q and K projections (z=0:Q, z=1:K), rounded outputs
    {
        dim3 grid(DD / 128, M / 128, 2);
        gemm_cp<128, 128, 32, 64, 32, false, true, false><<<grid, 256>>>(
            xt, w, bqk, qk, DD,
            DD, DD, DD,
            0, 0,
            (long long)WELE, 0,
            (long long)M * DD, 0,
            DD, 1, 1.0f);
    }
    // 1b) V projection, transposed + rounded into g_vt
    {
        dim3 grid(DD / 128, M / 128, 1);
        gemm_cp<128, 128, 32, 64, 32, false, true, true><<<grid, 256>>>(
            xt, w + 2 * WELE, wv_b, vt, DD,
            DD, DD, 0,
            0, 0, 0, 0, 0, 0, 0, 1, 1.0f);
    }

    // 2) scores[b,h] = SCALE * Q_h @ K_h^T  (into attn buffer, fp32)
    {
        dim3 grid(SS / 128, SS / 128, BB * HH);
        gemm_cp<128, 128, 32, 64, 32, false, false, false><<<grid, 256>>>(
            qk, qk + (long long)M * DD, nullptr, attn, DHH,
            DD, DD, SS,
            (long long)SS * DD, DHH,
            (long long)SS * DD, DHH,
            (long long)HH * SS * SS, (long long)SS * SS,
            0, HH, SCALE);
    }

    // 3) softmax rows in place (bit-packed mask, L2-resident)
    softmax_rows<<<(unsigned)((long long)BB * HH * SS), 256>>>(attn, pm);

    // 4) ctx = attn @ V  (A=attn rounded at load; B=vt k-contiguous)
    {
        dim3 grid(DHH / 64, SS / 128, BB * HH);
        gemm_cp<128, 64, 32, 32, 32, true, true, false><<<grid, 256>>>(
            attn, vt, nullptr, ctx, SS,
            SS, SS, DD,
            (long long)HH * SS * SS, (long long)SS * SS,
            (long long)DD * SS, (long long)DHH * SS,
            (long long)SS * DD, DHH,
            0, HH, 1.0f);
    }

    // 5) out = ctx @ wo^T + wo_b
    {
        dim3 grid(DD / 128, M / 128, 1);
        gemm_cp<128, 128, 32, 64, 32, false, false, false><<<grid, 256>>>(
            ctx, w + 3 * WELE, wo_b, out, DD,
            DD, DD, DD,
            0, 0, 0, 0, 0, 0, 0, 1, 1.0f);
    }
}